// round 14
// baseline (speedup 1.0000x reference)
#include <cuda_runtime.h>
#include <cuda_fp16.h>
#include <cstdint>

#define NN 4096
#define DQ 128
#define PW 128          // partial/U width: exactly 128 v-cols (den separate)
#define SPLITK 8
#define KCHUNK (NN / SPLITK)   // 512
#define KITERS (KCHUNK / 32)   // 16

// ---------------- scratch (static device globals; no allocation) ----------------
__device__ __half d_E[(size_t)NN * NN];                 // 32 MB: exp(trans) fp16, k-major
__device__ __half d_U[(size_t)NN * PW];                 // e^{sa}*v
__device__ __align__(16) __half d_part[(size_t)SPLITK * NN * PW];  // 8.4 MB fp16 split-K partials
__device__ float  d_denp[(size_t)SPLITK * NN];          // fp32 den partials
__device__ float  d_uvec[NN];                           // layer3: e^{sa}*(v . W_dec)
__device__ float  d_evec[NN];                           // per-layer e^{sa} (gemm den; layer3 gemv)
__device__ float  d_gemv_scratch[(size_t)2 * 64 * NN];  // layer3 gemv partials

// ---------------- PTX helpers ----------------
__device__ __forceinline__ uint32_t smem_u32(const void* p) {
    return (uint32_t)__cvta_generic_to_shared(p);
}
__device__ __forceinline__ void ldsm_x4t(uint32_t& r0, uint32_t& r1, uint32_t& r2, uint32_t& r3, uint32_t a) {
    asm volatile("ldmatrix.sync.aligned.m8n8.x4.trans.shared.b16 {%0,%1,%2,%3},[%4];"
                 : "=r"(r0), "=r"(r1), "=r"(r2), "=r"(r3) : "r"(a));
}
__device__ __forceinline__ void mma_f16(float& d0, float& d1, float& d2, float& d3,
                                        uint32_t a0, uint32_t a1, uint32_t a2, uint32_t a3,
                                        uint32_t b0, uint32_t b1) {
    asm volatile(
        "mma.sync.aligned.m16n8k16.row.col.f32.f16.f16.f32 "
        "{%0,%1,%2,%3},{%4,%5,%6,%7},{%8,%9},{%0,%1,%2,%3};"
        : "+f"(d0), "+f"(d1), "+f"(d2), "+f"(d3)
        : "r"(a0), "r"(a1), "r"(a2), "r"(a3), "r"(b0), "r"(b1));
}
__device__ __forceinline__ void cp16(uint32_t dst, const void* src) {
    asm volatile("cp.async.cg.shared.global [%0], [%1], 16;" :: "r"(dst), "l"(src));
}

// ---------------- 1. build E = exp(trans) elementwise ----------------
__global__ __launch_bounds__(256) void buildE_kernel(const float* __restrict__ trans)
{
    const size_t idx = ((size_t)blockIdx.x * 256 + threadIdx.x) * 8;
    float4 v0 = *(const float4*)(trans + idx);
    float4 v1 = *(const float4*)(trans + idx + 4);
    float e[8];
    e[0] = (v0.x == 0.f) ? 0.f : __expf(v0.x);
    e[1] = (v0.y == 0.f) ? 0.f : __expf(v0.y);
    e[2] = (v0.z == 0.f) ? 0.f : __expf(v0.z);
    e[3] = (v0.w == 0.f) ? 0.f : __expf(v0.w);
    e[4] = (v1.x == 0.f) ? 0.f : __expf(v1.x);
    e[5] = (v1.y == 0.f) ? 0.f : __expf(v1.y);
    e[6] = (v1.z == 0.f) ? 0.f : __expf(v1.z);
    e[7] = (v1.w == 0.f) ? 0.f : __expf(v1.w);
    __half2 h2[4];
#pragma unroll
    for (int i = 0; i < 4; i++)
        h2[i] = __floats2half2_rn(e[2 * i], e[2 * i + 1]);
    *(uint4*)(d_E + idx) = *(uint4*)h2;
}

// ---------------- 2. per-layer U; encode fused (layer 0) + warp-split weights ----------------
// grp0 (warps 0-3): W_ad path -> es_s, d_evec. grp1 (warps 4-7): W_av path -> d_U.
__global__ __launch_bounds__(256) void computeU_kernel(
    const float* __restrict__ W_ad, const float* __restrict__ b_ad,
    const float* __restrict__ wa,   const float* __restrict__ W_av,
    const float* __restrict__ b_av, int use_part,
    const float* __restrict__ W_dec,
    const float* __restrict__ x,    const float* __restrict__ comms,
    const float* __restrict__ W_enc, const float* __restrict__ b_enc)
{
    const int j0 = blockIdx.x * 16;
    const int tid = threadIdx.x;
    const int grp = tid >> 7;         // 0: att/d path, 1: v path
    const int c = tid & 127;
    __shared__ float hr[16][DQ];
    __shared__ float prod[16][DQ + 1];
    __shared__ float es_s[16];
    __shared__ float den[16];
    __shared__ float vdot[16];
    __shared__ float in[16][96];

    if (!use_part) {
        // fused encode: h = [x|comms] @ W_enc + b_enc for this block's 16 rows
        for (int idx = tid; idx < 16 * 64; idx += 256) {
            int r = idx >> 6, t = idx & 63;
            in[r][t] = x[(size_t)(j0 + r) * 64 + t];
        }
        for (int idx = tid; idx < 16 * 32; idx += 256) {
            int r = idx >> 5, t = idx & 31;
            in[r][64 + t] = comms[(size_t)(j0 + r) * 32 + t];
        }
        __syncthreads();
        const float be = b_enc[c];
        float ha[8];
#pragma unroll
        for (int r8 = 0; r8 < 8; r8++) ha[r8] = be;
#pragma unroll 4
        for (int t = 0; t < 96; t++) {
            float w = W_enc[t * DQ + c];
#pragma unroll
            for (int r8 = 0; r8 < 8; r8++) ha[r8] += in[grp * 8 + r8][t] * w;
        }
#pragma unroll
        for (int r8 = 0; r8 < 8; r8++) hr[grp * 8 + r8][c] = ha[r8];
        __syncthreads();
    } else {
        if (tid < 16) {
            float d = 0.f;
#pragma unroll
            for (int s = 0; s < SPLITK; s++)
                d += d_denp[(size_t)s * NN + j0 + tid];
            den[tid] = d;
        }
        // vectorized: thread owns (row = tid>>4, cols c8..c8+7); uint4 loads over splits
        const int pr = tid >> 4, c8 = (tid & 15) * 8;
        float a[8] = {0.f, 0.f, 0.f, 0.f, 0.f, 0.f, 0.f, 0.f};
#pragma unroll
        for (int s = 0; s < SPLITK; s++) {
            uint4 v = *(const uint4*)&d_part[((size_t)s * NN + j0 + pr) * PW + c8];
            const __half2* h = (const __half2*)&v;
#pragma unroll
            for (int q = 0; q < 4; q++) {
                float2 f = __half22float2(h[q]);
                a[2 * q] += f.x;
                a[2 * q + 1] += f.y;
            }
        }
        __syncthreads();   // den ready
        const float dinv = 1.f / den[pr];
#pragma unroll
        for (int q = 0; q < 8; q++) hr[pr][c8 + q] = a[q] * dinv;
        __syncthreads();
    }

    const float* W = grp ? W_av : W_ad;
    const float bb = grp ? b_av[c] : b_ad[c];
    float acc[16];
#pragma unroll
    for (int r = 0; r < 16; r++) acc[r] = bb;
#pragma unroll 4
    for (int t = 0; t < DQ; t++) {
        float w = W[t * DQ + c];
#pragma unroll
        for (int r = 0; r < 16; r++) acc[r] += hr[r][t] * w;
    }

    if (grp == 0) {
        const float wac = wa[c];
#pragma unroll
        for (int r = 0; r < 16; r++) prod[r][c] = acc[r] * wac;
    }
    __syncthreads();

    const int warp = tid >> 5, lane = tid & 31;
    if (grp == 0) {
#pragma unroll
        for (int rr = 0; rr < 4; rr++) {
            int r = warp * 4 + rr;
            float s = prod[r][lane] + prod[r][lane + 32] + prod[r][lane + 64] + prod[r][lane + 96];
#pragma unroll
            for (int o = 16; o > 0; o >>= 1) s += __shfl_xor_sync(0xffffffff, s, o);
            if (lane == 0) es_s[r] = __expf(s);
        }
    }
    __syncthreads();

    if (W_dec == nullptr) {
        if (grp == 1) {
#pragma unroll
            for (int r = 0; r < 16; r++)
                d_U[(size_t)(j0 + r) * PW + c] = __float2half(es_s[r] * acc[r]);
        } else if (c < 16) {
            d_evec[j0 + c] = es_s[c];
        }
    } else {
        if (grp == 1) {
            const float wdc = W_dec[c];
#pragma unroll
            for (int r = 0; r < 16; r++) prod[r][c] = acc[r] * wdc;
        }
        __syncthreads();
        if (grp == 1) {
#pragma unroll
            for (int rr = 0; rr < 4; rr++) {
                int r = (warp - 4) * 4 + rr;
                float s = prod[r][lane] + prod[r][lane + 32] + prod[r][lane + 64] + prod[r][lane + 96];
#pragma unroll
                for (int o = 16; o > 0; o >>= 1) s += __shfl_xor_sync(0xffffffff, s, o);
                if (lane == 0) vdot[r] = s;
            }
        }
        __syncthreads();
        if (grp == 0 && c < 16) {
            d_uvec[j0 + c] = es_s[c] * vdot[c];
            d_evec[j0 + c] = es_s[c];
        }
    }
}

// ---------------- 3. split-K fp16 GEMM: BM=128, BN=128, uint4 fused den ----------------
#define AST 136                            // 128 + 8 pad halfs
#define ABUF 4352                          // 32*136 halfs per buffer
#define SE_OFF (8 * ABUF)                  // floats after 8 half-buffers
#define GEMM_SMEM (8 * ABUF * 2 + (128 + 2048) * 4)

__global__ __launch_bounds__(256, 2) void gemm_kernel()
{
    extern __shared__ __half sm[];
    float* se = (float*)(sm + SE_OFF);          // [4][32]
    float* sden = se + 128;                     // [16][128]

    const int tid = threadIdx.x;
    const int m0 = blockIdx.x * 128;
    const size_t ks = (size_t)blockIdx.y * KCHUNK;
    const int warp = tid >> 5, lane = tid & 31;
    const int wm = (warp & 3) * 32, wn = (warp >> 2) * 64;

    float acc[2][8][4];
#pragma unroll
    for (int mi = 0; mi < 2; mi++)
#pragma unroll
        for (int i = 0; i < 8; i++)
            acc[mi][i][0] = acc[mi][i][1] = acc[mi][i][2] = acc[mi][i][3] = 0.f;
    float den[8] = {0.f, 0.f, 0.f, 0.f, 0.f, 0.f, 0.f, 0.f};

    const int r0 = tid >> 4, cc0 = (tid & 15) * 8;
    const int r1 = 16 + r0;
    const __half* Eg = d_E + ks * NN + m0;   // E[k][m]
    const __half* Ug = d_U + ks * PW;        // U[k][n]
    const float* ev = d_evec + ks;

#define ISSUE_STAGE(buf, kb)                                                      \
    do {                                                                          \
        const __half* Ea = Eg + (size_t)(kb) * NN;                                \
        const __half* Ua = Ug + (size_t)(kb) * PW;                                \
        cp16(smem_u32(&sm[(buf) * ABUF + r0 * AST + cc0]), Ea + (size_t)r0 * NN + cc0); \
        cp16(smem_u32(&sm[(buf) * ABUF + r1 * AST + cc0]), Ea + (size_t)r1 * NN + cc0); \
        cp16(smem_u32(&sm[(4 + (buf)) * ABUF + r0 * AST + cc0]), Ua + (size_t)r0 * PW + cc0); \
        cp16(smem_u32(&sm[(4 + (buf)) * ABUF + r1 * AST + cc0]), Ua + (size_t)r1 * PW + cc0); \
        if (tid >= 224) se[(buf) * 32 + tid - 224] = ev[(kb) + tid - 224];        \
        asm volatile("cp.async.commit_group;");                                   \
    } while (0)

    ISSUE_STAGE(0, 0);
    ISSUE_STAGE(1, 32);
    ISSUE_STAGE(2, 64);

    // den layout: thread owns 8 m's (m8) x 2 k's (kh2, kh2+1)
    const int m8 = (tid & 15) * 8, kh2 = (tid >> 4) * 2;

#pragma unroll 1
    for (int it = 0; it < KITERS; it++) {
        const int buf = it & 3;
        if (it < KITERS - 2)       asm volatile("cp.async.wait_group 2;" ::: "memory");
        else if (it == KITERS - 2) asm volatile("cp.async.wait_group 1;" ::: "memory");
        else                       asm volatile("cp.async.wait_group 0;" ::: "memory");
        __syncthreads();

        if (it + 3 < KITERS) ISSUE_STAGE((it + 3) & 3, (it + 3) * 32);

        // fused den (uint4): den[m8..m8+7] += E[k][m8..]*e[k] for k = kh2, kh2+1
#pragma unroll
        for (int k2 = 0; k2 < 2; k2++) {
            const int krow = kh2 + k2;
            uint4 v = *(const uint4*)&sm[buf * ABUF + krow * AST + m8];
            const float w = se[buf * 32 + krow];
            const __half2* h = (const __half2*)&v;
#pragma unroll
            for (int q = 0; q < 4; q++) {
                float2 f = __half22float2(h[q]);
                den[2 * q]     += f.x * w;
                den[2 * q + 1] += f.y * w;
            }
        }

#pragma unroll
        for (int kk = 0; kk < 2; kk++) {
            const int arow = kk * 16 + (lane & 7) + ((lane >> 4) << 3);
            const int acb = wm + ((lane >> 3) & 1) * 8;
            uint32_t a0[4], a1[4];
            ldsm_x4t(a0[0], a0[1], a0[2], a0[3],
                     smem_u32(&sm[buf * ABUF + arow * AST + acb]));
            ldsm_x4t(a1[0], a1[1], a1[2], a1[3],
                     smem_u32(&sm[buf * ABUF + arow * AST + acb + 16]));
#pragma unroll
            for (int nf = 0; nf < 4; nf++) {
                uint32_t b0, b1, b2, b3;
                ldsm_x4t(b0, b1, b2, b3,
                         smem_u32(&sm[(4 + buf) * ABUF + (kk * 16 + (lane & 15)) * AST
                                      + wn + nf * 16 + (lane >> 4) * 8]));
                float* c00 = acc[0][2 * nf];
                float* c01 = acc[0][2 * nf + 1];
                float* c10 = acc[1][2 * nf];
                float* c11 = acc[1][2 * nf + 1];
                mma_f16(c00[0], c00[1], c00[2], c00[3], a0[0], a0[1], a0[2], a0[3], b0, b1);
                mma_f16(c01[0], c01[1], c01[2], c01[3], a0[0], a0[1], a0[2], a0[3], b2, b3);
                mma_f16(c10[0], c10[1], c10[2], c10[3], a1[0], a1[1], a1[2], a1[3], b0, b1);
                mma_f16(c11[0], c11[1], c11[2], c11[3], a1[0], a1[1], a1[2], a1[3], b2, b3);
            }
        }
    }

    // epilogue: fp16 split partials + fp32 den partial
    const int g = lane >> 2, tg = lane & 3;
    __half* P = d_part + ((size_t)blockIdx.y * NN + m0 + wm) * PW + wn;
#pragma unroll
    for (int mi = 0; mi < 2; mi++) {
#pragma unroll
        for (int fi = 0; fi < 8; fi++) {
            int col = fi * 8 + tg * 2;
            int rr0 = mi * 16 + g;
            *(__half2*)&P[(size_t)rr0 * PW + col] =
                __floats2half2_rn(acc[mi][fi][0], acc[mi][fi][1]);
            *(__half2*)&P[(size_t)(rr0 + 8) * PW + col] =
                __floats2half2_rn(acc[mi][fi][2], acc[mi][fi][3]);
        }
    }
#pragma unroll
    for (int q = 0; q < 8; q++)
        sden[(tid >> 4) * 128 + m8 + q] = den[q];
    __syncthreads();
    if (tid < 128) {
        float s = 0.f;
#pragma unroll
        for (int gidx = 0; gidx < 16; gidx++) s += sden[gidx * 128 + tid];
        d_denp[(size_t)blockIdx.y * NN + m0 + tid] = s;
    }
#undef ISSUE_STAGE
}

// ---------------- 4. layer-3 GEMV: colsum of E weighted by u / e (R12 shape) ----------------
#define JCH 64
#define NJC (NN / JCH)  // 64 chunks
__global__ __launch_bounds__(256) void gemv_kernel()
{
    float* gnum = d_gemv_scratch;                // [NJC][NN]
    float* gden = gnum + (size_t)NJC * NN;
    const int i0 = blockIdx.x * 1024;
    const int j0 = blockIdx.y * JCH;
    const int t = threadIdx.x;
    __shared__ float su[JCH], sev[JCH];
    if (t < JCH) { su[t] = d_uvec[j0 + t]; sev[t] = d_evec[j0 + t]; }
    __syncthreads();

    float n0 = 0.f, n1 = 0.f, n2 = 0.f, n3 = 0.f;
    float e0 = 0.f, e1 = 0.f, e2 = 0.f, e3 = 0.f;
    const __half* Eb = d_E + (size_t)j0 * NN + i0 + 2 * t;
#pragma unroll 4
    for (int j = 0; j < JCH; j++) {
        const float u = su[j], evv = sev[j];
        const __half2 a = *(const __half2*)(Eb + (size_t)j * NN);
        const __half2 b = *(const __half2*)(Eb + (size_t)j * NN + 512);
        const float2 af = __half22float2(a);
        const float2 bf = __half22float2(b);
        n0 += af.x * u;   n1 += af.y * u;
        n2 += bf.x * u;   n3 += bf.y * u;
        e0 += af.x * evv; e1 += af.y * evv;
        e2 += bf.x * evv; e3 += bf.y * evv;
    }
    const size_t base = (size_t)blockIdx.y * NN + i0 + 2 * t;
    *(float2*)&gnum[base] = make_float2(n0, n1);
    *(float2*)&gnum[base + 512] = make_float2(n2, n3);
    *(float2*)&gden[base] = make_float2(e0, e1);
    *(float2*)&gden[base + 512] = make_float2(e2, e3);
}

// ---------------- 5. finalize: out = num/den + b_dec (+mask) ----------------
__global__ __launch_bounds__(128) void finalize_kernel(
    const float* __restrict__ b_dec, const int* __restrict__ mask,
    float* __restrict__ out)
{
    const float* gnum = d_gemv_scratch;
    const float* gden = gnum + (size_t)NJC * NN;
    const int i = blockIdx.x * 128 + threadIdx.x;
    float num = 0.f, den = 0.f;
#pragma unroll 8
    for (int jc = 0; jc < NJC; jc++) {
        num += gnum[(size_t)jc * NN + i];
        den += gden[(size_t)jc * NN + i];
    }
    out[i] = (mask[i] == 0) ? __int_as_float(0xff800000)
                            : (num / den + b_dec[0]);
}

// ---------------- launch ----------------
extern "C" void kernel_launch(void* const* d_in, const int* in_sizes, int n_in,
                              void* d_out, int out_size)
{
    const float* x      = (const float*)d_in[0];
    const float* comms  = (const float*)d_in[1];
    const float* trans  = (const float*)d_in[2];
    const int*   mask   = (const int*)d_in[3];
    const float* W_enc  = (const float*)d_in[4];
    const float* b_enc  = (const float*)d_in[5];
    const float* W_ad   = (const float*)d_in[6];
    const float* b_ad   = (const float*)d_in[7];
    const float* w_att  = (const float*)d_in[8];
    // d_in[9] = b_att: cancels in row-softmax, unused
    const float* W_av   = (const float*)d_in[10];
    const float* b_av   = (const float*)d_in[11];
    const float* W_dec  = (const float*)d_in[12];
    const float* b_dec  = (const float*)d_in[13];
    float* out = (float*)d_out;

    cudaFuncSetAttribute(gemm_kernel, cudaFuncAttributeMaxDynamicSharedMemorySize,
                         GEMM_SMEM);

    buildE_kernel<<<(NN * (size_t)NN) / (256 * 8), 256>>>(trans);

    for (int k = 0; k < 3; k++) {
        computeU_kernel<<<NN / 16, 256>>>(W_ad + (size_t)k * DQ * DQ,
                                          b_ad + (size_t)k * DQ,
                                          w_att + (size_t)k * 2 * DQ,   // wa = first half
                                          W_av + (size_t)k * DQ * DQ,
                                          b_av + (size_t)k * DQ,
                                          k > 0,
                                          (k == 2) ? W_dec : nullptr,
                                          x, comms, W_enc, b_enc);
        if (k < 2)
            gemm_kernel<<<dim3(NN / 128, SPLITK), 256, GEMM_SMEM>>>();
    }
    gemv_kernel<<<dim3(4, NJC), 256>>>();
    finalize_kernel<<<NN / 128, 128>>>(b_dec, mask, out);
}

// round 15
// speedup vs baseline: 1.3982x; 1.3982x over previous
#include <cuda_runtime.h>
#include <cuda_fp16.h>
#include <cstdint>

#define NN 4096
#define DQ 128
#define PW 128          // partial/U width: exactly 128 v-cols (den separate)
#define SPLITK 8
#define KCHUNK (NN / SPLITK)   // 512
#define KITERS (KCHUNK / 32)   // 16

// ---------------- scratch (static device globals; no allocation) ----------------
__device__ __half d_E[(size_t)NN * NN];                 // 32 MB: exp(trans) fp16, k-major
__device__ float  d_h[(size_t)NN * DQ];                 // encoder output (layer 0 input)
__device__ __half d_U[(size_t)NN * PW];                 // e^{sa}*v
__device__ __align__(16) __half d_part[(size_t)SPLITK * NN * PW];  // 8.4 MB fp16 split-K partials
__device__ float  d_denp[(size_t)SPLITK * NN];          // fp32 den partials
__device__ float  d_uvec[NN];                           // layer3: e^{sa}*(v . W_dec)
__device__ float  d_evec[NN];                           // per-layer e^{sa} (gemm den; layer3 gemv)
__device__ float  d_gemv_scratch[(size_t)2 * 64 * NN];  // layer3 gemv partials

// ---------------- PTX helpers ----------------
__device__ __forceinline__ uint32_t smem_u32(const void* p) {
    return (uint32_t)__cvta_generic_to_shared(p);
}
__device__ __forceinline__ void ldsm_x4t(uint32_t& r0, uint32_t& r1, uint32_t& r2, uint32_t& r3, uint32_t a) {
    asm volatile("ldmatrix.sync.aligned.m8n8.x4.trans.shared.b16 {%0,%1,%2,%3},[%4];"
                 : "=r"(r0), "=r"(r1), "=r"(r2), "=r"(r3) : "r"(a));
}
__device__ __forceinline__ void mma_f16(float& d0, float& d1, float& d2, float& d3,
                                        uint32_t a0, uint32_t a1, uint32_t a2, uint32_t a3,
                                        uint32_t b0, uint32_t b1) {
    asm volatile(
        "mma.sync.aligned.m16n8k16.row.col.f32.f16.f16.f32 "
        "{%0,%1,%2,%3},{%4,%5,%6,%7},{%8,%9},{%0,%1,%2,%3};"
        : "+f"(d0), "+f"(d1), "+f"(d2), "+f"(d3)
        : "r"(a0), "r"(a1), "r"(a2), "r"(a3), "r"(b0), "r"(b1));
}
__device__ __forceinline__ void cp16(uint32_t dst, const void* src) {
    asm volatile("cp.async.cg.shared.global [%0], [%1], 16;" :: "r"(dst), "l"(src));
}

// ---------------- 1. encode: h = [x|comms] @ W_enc + b_enc ----------------
__global__ __launch_bounds__(128) void encode_kernel(
    const float* __restrict__ x, const float* __restrict__ comms,
    const float* __restrict__ W_enc, const float* __restrict__ b_enc)
{
    const int i0 = blockIdx.x * 16;
    const int c = threadIdx.x;
    __shared__ float in[16][96];
    for (int idx = c; idx < 16 * 64; idx += 128) {
        int r = idx >> 6, t = idx & 63;
        in[r][t] = x[(size_t)(i0 + r) * 64 + t];
    }
    for (int idx = c; idx < 16 * 32; idx += 128) {
        int r = idx >> 5, t = idx & 31;
        in[r][64 + t] = comms[(size_t)(i0 + r) * 32 + t];
    }
    __syncthreads();
    float acc[16];
    const float be = b_enc[c];
#pragma unroll
    for (int r = 0; r < 16; r++) acc[r] = be;
#pragma unroll 4
    for (int t = 0; t < 96; t++) {
        float w = W_enc[t * DQ + c];
#pragma unroll
        for (int r = 0; r < 16; r++) acc[r] += in[r][t] * w;
    }
#pragma unroll
    for (int r = 0; r < 16; r++) d_h[(size_t)(i0 + r) * DQ + c] = acc[r];
}

// ---------------- 2. build E = exp(trans) elementwise ----------------
__global__ __launch_bounds__(256) void buildE_kernel(const float* __restrict__ trans)
{
    const size_t idx = ((size_t)blockIdx.x * 256 + threadIdx.x) * 8;
    float4 v0 = *(const float4*)(trans + idx);
    float4 v1 = *(const float4*)(trans + idx + 4);
    float e[8];
    e[0] = (v0.x == 0.f) ? 0.f : __expf(v0.x);
    e[1] = (v0.y == 0.f) ? 0.f : __expf(v0.y);
    e[2] = (v0.z == 0.f) ? 0.f : __expf(v0.z);
    e[3] = (v0.w == 0.f) ? 0.f : __expf(v0.w);
    e[4] = (v1.x == 0.f) ? 0.f : __expf(v1.x);
    e[5] = (v1.y == 0.f) ? 0.f : __expf(v1.y);
    e[6] = (v1.z == 0.f) ? 0.f : __expf(v1.z);
    e[7] = (v1.w == 0.f) ? 0.f : __expf(v1.w);
    __half2 h2[4];
#pragma unroll
    for (int i = 0; i < 4; i++)
        h2[i] = __floats2half2_rn(e[2 * i], e[2 * i + 1]);
    *(uint4*)(d_E + idx) = *(uint4*)h2;
}

// ---------------- 3. per-layer U; float4-hr weight loop + warp-split ----------------
// grp0 (warps 0-3): W_ad path -> es_s, d_evec. grp1 (warps 4-7): W_av path -> d_U.
__global__ __launch_bounds__(256) void computeU_kernel(
    const float* __restrict__ W_ad, const float* __restrict__ b_ad,
    const float* __restrict__ wa,   const float* __restrict__ W_av,
    const float* __restrict__ b_av, int use_part,
    const float* __restrict__ W_dec)
{
    const int j0 = blockIdx.x * 16;
    const int tid = threadIdx.x;
    const int grp = tid >> 7;         // 0: att/d path, 1: v path
    const int c = tid & 127;
    __shared__ __align__(16) float hr[16][DQ];
    __shared__ float prod[16][DQ + 1];
    __shared__ float es_s[16];
    __shared__ float den[16];
    __shared__ float vdot[16];

    if (!use_part) {
#pragma unroll
        for (int r8 = 0; r8 < 8; r8++) {
            int r = grp * 8 + r8;
            hr[r][c] = d_h[(size_t)(j0 + r) * DQ + c];
        }
        __syncthreads();
    } else {
        if (tid < 16) {
            float d = 0.f;
#pragma unroll
            for (int s = 0; s < SPLITK; s++)
                d += d_denp[(size_t)s * NN + j0 + tid];
            den[tid] = d;
        }
        // vectorized: thread owns (row = tid>>4, cols c8..c8+7); uint4 loads over splits
        const int pr = tid >> 4, c8 = (tid & 15) * 8;
        float a[8] = {0.f, 0.f, 0.f, 0.f, 0.f, 0.f, 0.f, 0.f};
#pragma unroll
        for (int s = 0; s < SPLITK; s++) {
            uint4 v = *(const uint4*)&d_part[((size_t)s * NN + j0 + pr) * PW + c8];
            const __half2* h = (const __half2*)&v;
#pragma unroll
            for (int q = 0; q < 4; q++) {
                float2 f = __half22float2(h[q]);
                a[2 * q] += f.x;
                a[2 * q + 1] += f.y;
            }
        }
        __syncthreads();   // den ready
        const float dinv = 1.f / den[pr];
#pragma unroll
        for (int q = 0; q < 8; q++) hr[pr][c8 + q] = a[q] * dinv;
        __syncthreads();
    }

    const float* W = grp ? W_av : W_ad;
    const float bb = grp ? b_av[c] : b_ad[c];
    float acc[16];
#pragma unroll
    for (int r = 0; r < 16; r++) acc[r] = bb;
    // float4-hr: unroll t by 4, one LDS.128 broadcast per (r, t4) -> 4x fewer LDS
#pragma unroll 2
    for (int t4 = 0; t4 < DQ / 4; t4++) {
        const float w0 = W[(4 * t4 + 0) * DQ + c];
        const float w1 = W[(4 * t4 + 1) * DQ + c];
        const float w2 = W[(4 * t4 + 2) * DQ + c];
        const float w3 = W[(4 * t4 + 3) * DQ + c];
#pragma unroll
        for (int r = 0; r < 16; r++) {
            const float4 h4 = *(const float4*)&hr[r][4 * t4];
            acc[r] += h4.x * w0 + h4.y * w1 + h4.z * w2 + h4.w * w3;
        }
    }

    if (grp == 0) {
        const float wac = wa[c];
#pragma unroll
        for (int r = 0; r < 16; r++) prod[r][c] = acc[r] * wac;
    }
    __syncthreads();

    const int warp = tid >> 5, lane = tid & 31;
    if (grp == 0) {
#pragma unroll
        for (int rr = 0; rr < 4; rr++) {
            int r = warp * 4 + rr;
            float s = prod[r][lane] + prod[r][lane + 32] + prod[r][lane + 64] + prod[r][lane + 96];
#pragma unroll
            for (int o = 16; o > 0; o >>= 1) s += __shfl_xor_sync(0xffffffff, s, o);
            if (lane == 0) es_s[r] = __expf(s);
        }
    }
    __syncthreads();

    if (W_dec == nullptr) {
        if (grp == 1) {
#pragma unroll
            for (int r = 0; r < 16; r++)
                d_U[(size_t)(j0 + r) * PW + c] = __float2half(es_s[r] * acc[r]);
        } else if (c < 16) {
            d_evec[j0 + c] = es_s[c];
        }
    } else {
        if (grp == 1) {
            const float wdc = W_dec[c];
#pragma unroll
            for (int r = 0; r < 16; r++) prod[r][c] = acc[r] * wdc;
        }
        __syncthreads();
        if (grp == 1) {
#pragma unroll
            for (int rr = 0; rr < 4; rr++) {
                int r = (warp - 4) * 4 + rr;
                float s = prod[r][lane] + prod[r][lane + 32] + prod[r][lane + 64] + prod[r][lane + 96];
#pragma unroll
                for (int o = 16; o > 0; o >>= 1) s += __shfl_xor_sync(0xffffffff, s, o);
                if (lane == 0) vdot[r] = s;
            }
        }
        __syncthreads();
        if (grp == 0 && c < 16) {
            d_uvec[j0 + c] = es_s[c] * vdot[c];
            d_evec[j0 + c] = es_s[c];
        }
    }
}

// ---------------- 4. split-K fp16 GEMM: BM=128, BN=128, fused den (half2) ----------------
#define AST 136                            // 128 + 8 pad halfs
#define ABUF 4352                          // 32*136 halfs per buffer
#define SE_OFF (8 * ABUF)                  // floats after 8 half-buffers
#define GEMM_SMEM (8 * ABUF * 2 + (128 + 512) * 4)

__global__ __launch_bounds__(256, 2) void gemm_kernel()
{
    extern __shared__ __half sm[];
    float* se = (float*)(sm + SE_OFF);          // [4][32]
    float* sden = se + 128;                     // [4][128]

    const int tid = threadIdx.x;
    const int m0 = blockIdx.x * 128;
    const size_t ks = (size_t)blockIdx.y * KCHUNK;
    const int warp = tid >> 5, lane = tid & 31;
    const int wm = (warp & 3) * 32, wn = (warp >> 2) * 64;

    float acc[2][8][4];
#pragma unroll
    for (int mi = 0; mi < 2; mi++)
#pragma unroll
        for (int i = 0; i < 8; i++)
            acc[mi][i][0] = acc[mi][i][1] = acc[mi][i][2] = acc[mi][i][3] = 0.f;
    float den0 = 0.f, den1 = 0.f;

    const int r0 = tid >> 4, cc0 = (tid & 15) * 8;
    const int r1 = 16 + r0;
    const __half* Eg = d_E + ks * NN + m0;   // E[k][m]
    const __half* Ug = d_U + ks * PW;        // U[k][n]
    const float* ev = d_evec + ks;

#define ISSUE_STAGE(buf, kb)                                                      \
    do {                                                                          \
        const __half* Ea = Eg + (size_t)(kb) * NN;                                \
        const __half* Ua = Ug + (size_t)(kb) * PW;                                \
        cp16(smem_u32(&sm[(buf) * ABUF + r0 * AST + cc0]), Ea + (size_t)r0 * NN + cc0); \
        cp16(smem_u32(&sm[(buf) * ABUF + r1 * AST + cc0]), Ea + (size_t)r1 * NN + cc0); \
        cp16(smem_u32(&sm[(4 + (buf)) * ABUF + r0 * AST + cc0]), Ua + (size_t)r0 * PW + cc0); \
        cp16(smem_u32(&sm[(4 + (buf)) * ABUF + r1 * AST + cc0]), Ua + (size_t)r1 * PW + cc0); \
        if (tid >= 224) se[(buf) * 32 + tid - 224] = ev[(kb) + tid - 224];        \
        asm volatile("cp.async.commit_group;");                                   \
    } while (0)

    ISSUE_STAGE(0, 0);
    ISSUE_STAGE(1, 32);
    ISSUE_STAGE(2, 64);

    const int m2 = (tid & 63) * 2, kh = (tid >> 6) * 8;

#pragma unroll 1
    for (int it = 0; it < KITERS; it++) {
        const int buf = it & 3;
        if (it < KITERS - 2)       asm volatile("cp.async.wait_group 2;" ::: "memory");
        else if (it == KITERS - 2) asm volatile("cp.async.wait_group 1;" ::: "memory");
        else                       asm volatile("cp.async.wait_group 0;" ::: "memory");
        __syncthreads();

        if (it + 3 < KITERS) ISSUE_STAGE((it + 3) & 3, (it + 3) * 32);

#pragma unroll
        for (int k2 = 0; k2 < 8; k2++) {
            const float2 ef = __half22float2(
                *(const __half2*)&sm[buf * ABUF + (kh + k2) * AST + m2]);
            const float w = se[buf * 32 + kh + k2];
            den0 += ef.x * w;
            den1 += ef.y * w;
        }

#pragma unroll
        for (int kk = 0; kk < 2; kk++) {
            const int arow = kk * 16 + (lane & 7) + ((lane >> 4) << 3);
            const int acb = wm + ((lane >> 3) & 1) * 8;
            uint32_t a0[4], a1[4];
            ldsm_x4t(a0[0], a0[1], a0[2], a0[3],
                     smem_u32(&sm[buf * ABUF + arow * AST + acb]));
            ldsm_x4t(a1[0], a1[1], a1[2], a1[3],
                     smem_u32(&sm[buf * ABUF + arow * AST + acb + 16]));
#pragma unroll
            for (int nf = 0; nf < 4; nf++) {
                uint32_t b0, b1, b2, b3;
                ldsm_x4t(b0, b1, b2, b3,
                         smem_u32(&sm[(4 + buf) * ABUF + (kk * 16 + (lane & 15)) * AST
                                      + wn + nf * 16 + (lane >> 4) * 8]));
                float* c00 = acc[0][2 * nf];
                float* c01 = acc[0][2 * nf + 1];
                float* c10 = acc[1][2 * nf];
                float* c11 = acc[1][2 * nf + 1];
                mma_f16(c00[0], c00[1], c00[2], c00[3], a0[0], a0[1], a0[2], a0[3], b0, b1);
                mma_f16(c01[0], c01[1], c01[2], c01[3], a0[0], a0[1], a0[2], a0[3], b2, b3);
                mma_f16(c10[0], c10[1], c10[2], c10[3], a1[0], a1[1], a1[2], a1[3], b0, b1);
                mma_f16(c11[0], c11[1], c11[2], c11[3], a1[0], a1[1], a1[2], a1[3], b2, b3);
            }
        }
    }

    const int g = lane >> 2, tg = lane & 3;
    __half* P = d_part + ((size_t)blockIdx.y * NN + m0 + wm) * PW + wn;
#pragma unroll
    for (int mi = 0; mi < 2; mi++) {
#pragma unroll
        for (int fi = 0; fi < 8; fi++) {
            int col = fi * 8 + tg * 2;
            int rr0 = mi * 16 + g;
            *(__half2*)&P[(size_t)rr0 * PW + col] =
                __floats2half2_rn(acc[mi][fi][0], acc[mi][fi][1]);
            *(__half2*)&P[(size_t)(rr0 + 8) * PW + col] =
                __floats2half2_rn(acc[mi][fi][2], acc[mi][fi][3]);
        }
    }
    sden[(tid >> 6) * 128 + m2] = den0;
    sden[(tid >> 6) * 128 + m2 + 1] = den1;
    __syncthreads();
    if (tid < 128)
        d_denp[(size_t)blockIdx.y * NN + m0 + tid] =
            sden[tid] + sden[128 + tid] + sden[256 + tid] + sden[384 + tid];
#undef ISSUE_STAGE
}

// ---------------- 5. layer-3 GEMV: colsum of E weighted by u / e ----------------
#define JCH 64
#define NJC (NN / JCH)  // 64 chunks
__global__ __launch_bounds__(256) void gemv_kernel()
{
    float* gnum = d_gemv_scratch;                // [NJC][NN]
    float* gden = gnum + (size_t)NJC * NN;
    const int i0 = blockIdx.x * 1024;
    const int j0 = blockIdx.y * JCH;
    const int t = threadIdx.x;
    __shared__ float su[JCH], sev[JCH];
    if (t < JCH) { su[t] = d_uvec[j0 + t]; sev[t] = d_evec[j0 + t]; }
    __syncthreads();

    float n0 = 0.f, n1 = 0.f, n2 = 0.f, n3 = 0.f;
    float e0 = 0.f, e1 = 0.f, e2 = 0.f, e3 = 0.f;
    const __half* Eb = d_E + (size_t)j0 * NN + i0 + 2 * t;
#pragma unroll 4
    for (int j = 0; j < JCH; j++) {
        const float u = su[j], evv = sev[j];
        const __half2 a = *(const __half2*)(Eb + (size_t)j * NN);
        const __half2 b = *(const __half2*)(Eb + (size_t)j * NN + 512);
        const float2 af = __half22float2(a);
        const float2 bf = __half22float2(b);
        n0 += af.x * u;   n1 += af.y * u;
        n2 += bf.x * u;   n3 += bf.y * u;
        e0 += af.x * evv; e1 += af.y * evv;
        e2 += bf.x * evv; e3 += bf.y * evv;
    }
    const size_t base = (size_t)blockIdx.y * NN + i0 + 2 * t;
    *(float2*)&gnum[base] = make_float2(n0, n1);
    *(float2*)&gnum[base + 512] = make_float2(n2, n3);
    *(float2*)&gden[base] = make_float2(e0, e1);
    *(float2*)&gden[base + 512] = make_float2(e2, e3);
}

// ---------------- 6. finalize: out = num/den + b_dec (+mask) ----------------
__global__ __launch_bounds__(128) void finalize_kernel(
    const float* __restrict__ b_dec, const int* __restrict__ mask,
    float* __restrict__ out)
{
    const float* gnum = d_gemv_scratch;
    const float* gden = gnum + (size_t)NJC * NN;
    const int i = blockIdx.x * 128 + threadIdx.x;
    float num = 0.f, den = 0.f;
#pragma unroll 8
    for (int jc = 0; jc < NJC; jc++) {
        num += gnum[(size_t)jc * NN + i];
        den += gden[(size_t)jc * NN + i];
    }
    out[i] = (mask[i] == 0) ? __int_as_float(0xff800000)
                            : (num / den + b_dec[0]);
}

// ---------------- launch ----------------
extern "C" void kernel_launch(void* const* d_in, const int* in_sizes, int n_in,
                              void* d_out, int out_size)
{
    const float* x      = (const float*)d_in[0];
    const float* comms  = (const float*)d_in[1];
    const float* trans  = (const float*)d_in[2];
    const int*   mask   = (const int*)d_in[3];
    const float* W_enc  = (const float*)d_in[4];
    const float* b_enc  = (const float*)d_in[5];
    const float* W_ad   = (const float*)d_in[6];
    const float* b_ad   = (const float*)d_in[7];
    const float* w_att  = (const float*)d_in[8];
    // d_in[9] = b_att: cancels in row-softmax, unused
    const float* W_av   = (const float*)d_in[10];
    const float* b_av   = (const float*)d_in[11];
    const float* W_dec  = (const float*)d_in[12];
    const float* b_dec  = (const float*)d_in[13];
    float* out = (float*)d_out;

    cudaFuncSetAttribute(gemm_kernel, cudaFuncAttributeMaxDynamicSharedMemorySize,
                         GEMM_SMEM);

    encode_kernel<<<NN / 16, 128>>>(x, comms, W_enc, b_enc);
    buildE_kernel<<<(NN * (size_t)NN) / (256 * 8), 256>>>(trans);

    for (int k = 0; k < 3; k++) {
        computeU_kernel<<<NN / 16, 256>>>(W_ad + (size_t)k * DQ * DQ,
                                          b_ad + (size_t)k * DQ,
                                          w_att + (size_t)k * 2 * DQ,   // wa = first half
                                          W_av + (size_t)k * DQ * DQ,
                                          b_av + (size_t)k * DQ,
                                          k > 0,
                                          (k == 2) ? W_dec : nullptr);
        if (k < 2)
            gemm_kernel<<<dim3(NN / 128, SPLITK), 256, GEMM_SMEM>>>();
    }
    gemv_kernel<<<dim3(4, NJC), 256>>>();
    finalize_kernel<<<NN / 128, 128>>>(b_dec, mask, out);
}

// round 16
// speedup vs baseline: 1.8409x; 1.3166x over previous
#include <cuda_runtime.h>
#include <cuda_fp16.h>
#include <cstdint>

#define NN 4096
#define DQ 128
#define PW 128          // partial/U width: exactly 128 v-cols (den separate)
#define SPLITK 8
#define KCHUNK (NN / SPLITK)   // 512
#define KITERS (KCHUNK / 32)   // 16

// ---------------- scratch (static device globals; no allocation) ----------------
__device__ __half d_E[(size_t)NN * NN];                 // 32 MB: exp(trans) fp16, k-major
__device__ float  d_h[(size_t)NN * DQ];                 // encoder output (layer 0 input)
__device__ __half d_U[(size_t)NN * PW];                 // e^{sa}*v
__device__ __align__(16) __half d_part[(size_t)SPLITK * NN * PW];  // 8.4 MB fp16 split-K partials
__device__ float  d_denp[(size_t)SPLITK * NN];          // fp32 den partials
__device__ float  d_uvec[NN];                           // layer3: e^{sa}*(v . W_dec)
__device__ float  d_evec[NN];                           // per-layer e^{sa} (gemm den; layer3 gemv)
__device__ float  d_gemv_scratch[(size_t)2 * 64 * NN];  // layer3 gemv partials

// ---------------- PTX helpers ----------------
__device__ __forceinline__ uint32_t smem_u32(const void* p) {
    return (uint32_t)__cvta_generic_to_shared(p);
}
__device__ __forceinline__ void ldsm_x4(uint32_t& r0, uint32_t& r1, uint32_t& r2, uint32_t& r3, uint32_t a) {
    asm volatile("ldmatrix.sync.aligned.m8n8.x4.shared.b16 {%0,%1,%2,%3},[%4];"
                 : "=r"(r0), "=r"(r1), "=r"(r2), "=r"(r3) : "r"(a));
}
__device__ __forceinline__ void ldsm_x4t(uint32_t& r0, uint32_t& r1, uint32_t& r2, uint32_t& r3, uint32_t a) {
    asm volatile("ldmatrix.sync.aligned.m8n8.x4.trans.shared.b16 {%0,%1,%2,%3},[%4];"
                 : "=r"(r0), "=r"(r1), "=r"(r2), "=r"(r3) : "r"(a));
}
__device__ __forceinline__ void mma_f16(float& d0, float& d1, float& d2, float& d3,
                                        uint32_t a0, uint32_t a1, uint32_t a2, uint32_t a3,
                                        uint32_t b0, uint32_t b1) {
    asm volatile(
        "mma.sync.aligned.m16n8k16.row.col.f32.f16.f16.f32 "
        "{%0,%1,%2,%3},{%4,%5,%6,%7},{%8,%9},{%0,%1,%2,%3};"
        : "+f"(d0), "+f"(d1), "+f"(d2), "+f"(d3)
        : "r"(a0), "r"(a1), "r"(a2), "r"(a3), "r"(b0), "r"(b1));
}
__device__ __forceinline__ void cp16(uint32_t dst, const void* src) {
    asm volatile("cp.async.cg.shared.global [%0], [%1], 16;" :: "r"(dst), "l"(src));
}

// ---------------- 1. encode: h = [x|comms] @ W_enc + b_enc ----------------
__global__ __launch_bounds__(128) void encode_kernel(
    const float* __restrict__ x, const float* __restrict__ comms,
    const float* __restrict__ W_enc, const float* __restrict__ b_enc)
{
    const int i0 = blockIdx.x * 16;
    const int c = threadIdx.x;
    __shared__ float in[16][96];
    for (int idx = c; idx < 16 * 64; idx += 128) {
        int r = idx >> 6, t = idx & 63;
        in[r][t] = x[(size_t)(i0 + r) * 64 + t];
    }
    for (int idx = c; idx < 16 * 32; idx += 128) {
        int r = idx >> 5, t = idx & 31;
        in[r][64 + t] = comms[(size_t)(i0 + r) * 32 + t];
    }
    __syncthreads();
    float acc[16];
    const float be = b_enc[c];
#pragma unroll
    for (int r = 0; r < 16; r++) acc[r] = be;
#pragma unroll 4
    for (int t = 0; t < 96; t++) {
        float w = W_enc[t * DQ + c];
#pragma unroll
        for (int r = 0; r < 16; r++) acc[r] += in[r][t] * w;
    }
#pragma unroll
    for (int r = 0; r < 16; r++) d_h[(size_t)(i0 + r) * DQ + c] = acc[r];
}

// ---------------- 2. build E = exp(trans) elementwise ----------------
__global__ __launch_bounds__(256) void buildE_kernel(const float* __restrict__ trans)
{
    const size_t idx = ((size_t)blockIdx.x * 256 + threadIdx.x) * 8;
    float4 v0 = *(const float4*)(trans + idx);
    float4 v1 = *(const float4*)(trans + idx + 4);
    float e[8];
    e[0] = (v0.x == 0.f) ? 0.f : __expf(v0.x);
    e[1] = (v0.y == 0.f) ? 0.f : __expf(v0.y);
    e[2] = (v0.z == 0.f) ? 0.f : __expf(v0.z);
    e[3] = (v0.w == 0.f) ? 0.f : __expf(v0.w);
    e[4] = (v1.x == 0.f) ? 0.f : __expf(v1.x);
    e[5] = (v1.y == 0.f) ? 0.f : __expf(v1.y);
    e[6] = (v1.z == 0.f) ? 0.f : __expf(v1.z);
    e[7] = (v1.w == 0.f) ? 0.f : __expf(v1.w);
    __half2 h2[4];
#pragma unroll
    for (int i = 0; i < 4; i++)
        h2[i] = __floats2half2_rn(e[2 * i], e[2 * i + 1]);
    *(uint4*)(d_E + idx) = *(uint4*)h2;
}

// ---------------- 3. per-layer U via tensor cores ----------------
// A = h-tile (16x128 fp16), B = W_ad / W_av (fp32 -> fp16 staged per k-step).
// 8 warps, each owns 16 n-cols; biases + wa/es applied in epilogue.
#define WST 136
__global__ __launch_bounds__(256) void computeU_kernel(
    const float* __restrict__ W_ad, const float* __restrict__ b_ad,
    const float* __restrict__ wa,   const float* __restrict__ W_av,
    const float* __restrict__ b_av, int use_part,
    const float* __restrict__ W_dec)
{
    const int j0 = blockIdx.x * 16;
    const int tid = threadIdx.x;
    const int warp = tid >> 5, lane = tid & 31;
    __shared__ __align__(16) __half a_s[16][WST];
    __shared__ __align__(16) __half w_s[2][2][16][WST];
    __shared__ float prod[16][DQ + 1];
    __shared__ float es_s[16];
    __shared__ float den[16];
    __shared__ float vdot[16];
    __shared__ float swa[128], sbad[128], sbav[128], swd[128];

    // stage small vectors
    if (tid < 128) {
        swa[tid] = wa[tid];
        sbad[tid] = b_ad[tid];
        sbav[tid] = b_av[tid];
        swd[tid] = (W_dec != nullptr) ? W_dec[tid] : 0.f;
    }

    // ---- phase 1: build A (fp16 h-tile) ----
    if (!use_part) {
        const int grp = tid >> 7, c = tid & 127;
#pragma unroll
        for (int r8 = 0; r8 < 8; r8++) {
            int r = grp * 8 + r8;
            a_s[r][c] = __float2half(d_h[(size_t)(j0 + r) * DQ + c]);
        }
    } else {
        if (tid < 16) {
            float d = 0.f;
#pragma unroll
            for (int s = 0; s < SPLITK; s++)
                d += d_denp[(size_t)s * NN + j0 + tid];
            den[tid] = d;
        }
        const int pr = tid >> 4, c8 = (tid & 15) * 8;
        float a[8] = {0.f, 0.f, 0.f, 0.f, 0.f, 0.f, 0.f, 0.f};
#pragma unroll
        for (int s = 0; s < SPLITK; s++) {
            uint4 v = *(const uint4*)&d_part[((size_t)s * NN + j0 + pr) * PW + c8];
            const __half2* h = (const __half2*)&v;
#pragma unroll
            for (int q = 0; q < 4; q++) {
                float2 f = __half22float2(h[q]);
                a[2 * q] += f.x;
                a[2 * q + 1] += f.y;
            }
        }
        __syncthreads();   // den ready
        const float dinv = 1.f / den[pr];
#pragma unroll
        for (int q = 0; q < 8; q++)
            a_s[pr][c8 + q] = __float2half(a[q] * dinv);
    }

    // ---- phase 2: staged-W mma over 8 k-steps ----
    float2 wreg[8];
#define LOADW(ks)                                                              \
    do {                                                                       \
        _Pragma("unroll")                                                      \
        for (int e = 0; e < 8; e++) {                                          \
            int idx = 2 * tid + 512 * e;                                       \
            const float* Wsrc = (idx & 2048) ? W_av : W_ad;                    \
            int t = (idx >> 7) & 15, cc = idx & 127;                           \
            wreg[e] = *(const float2*)&Wsrc[((ks) * 16 + t) * DQ + cc];        \
        }                                                                      \
    } while (0)
#define STOREW(buf)                                                            \
    do {                                                                       \
        _Pragma("unroll")                                                      \
        for (int e = 0; e < 8; e++) {                                          \
            int idx = 2 * tid + 512 * e;                                       \
            int mat = (idx >> 11) & 1, t = (idx >> 7) & 15, cc = idx & 127;    \
            *(__half2*)&w_s[buf][mat][t][cc] =                                 \
                __floats2half2_rn(wreg[e].x, wreg[e].y);                       \
        }                                                                      \
    } while (0)

    float accd[2][4], accv[2][4];
#pragma unroll
    for (int nf = 0; nf < 2; nf++)
#pragma unroll
        for (int q = 0; q < 4; q++) { accd[nf][q] = 0.f; accv[nf][q] = 0.f; }

    LOADW(0);
    STOREW(0);
#pragma unroll 1
    for (int ks = 0; ks < 8; ks++) {
        const int buf = ks & 1;
        if (ks + 1 < 8) LOADW(ks + 1);
        __syncthreads();   // w_s[buf] + (first iter) a_s visible
        uint32_t a0, a1, a2, a3;
        ldsm_x4(a0, a1, a2, a3,
                smem_u32(&a_s[lane & 15][ks * 16 + (lane >> 4) * 8]));
        uint32_t bd0, bd1, bd2, bd3, bv0, bv1, bv2, bv3;
        ldsm_x4t(bd0, bd1, bd2, bd3,
                 smem_u32(&w_s[buf][0][lane & 15][warp * 16 + (lane >> 4) * 8]));
        ldsm_x4t(bv0, bv1, bv2, bv3,
                 smem_u32(&w_s[buf][1][lane & 15][warp * 16 + (lane >> 4) * 8]));
        mma_f16(accd[0][0], accd[0][1], accd[0][2], accd[0][3], a0, a1, a2, a3, bd0, bd1);
        mma_f16(accd[1][0], accd[1][1], accd[1][2], accd[1][3], a0, a1, a2, a3, bd2, bd3);
        mma_f16(accv[0][0], accv[0][1], accv[0][2], accv[0][3], a0, a1, a2, a3, bv0, bv1);
        mma_f16(accv[1][0], accv[1][1], accv[1][2], accv[1][3], a0, a1, a2, a3, bv2, bv3);
        if (ks + 1 < 8) STOREW(buf ^ 1);   // buf^1 last read at ks-1; all passed sync
    }
#undef LOADW
#undef STOREW

    // ---- phase 3: att reduction -> es ----
    const int g = lane >> 2, tg = lane & 3;
#pragma unroll
    for (int nf = 0; nf < 2; nf++) {
        const int cb = warp * 16 + nf * 8 + tg * 2;
        prod[g][cb]     = (accd[nf][0] + sbad[cb])     * swa[cb];
        prod[g][cb + 1] = (accd[nf][1] + sbad[cb + 1]) * swa[cb + 1];
        prod[g + 8][cb]     = (accd[nf][2] + sbad[cb])     * swa[cb];
        prod[g + 8][cb + 1] = (accd[nf][3] + sbad[cb + 1]) * swa[cb + 1];
    }
    __syncthreads();
    if (tid < 128) {
        const int rw = tid >> 5, rl = tid & 31;
#pragma unroll
        for (int rr = 0; rr < 4; rr++) {
            int r = rw * 4 + rr;
            float s = prod[r][rl] + prod[r][rl + 32] + prod[r][rl + 64] + prod[r][rl + 96];
#pragma unroll
            for (int o = 16; o > 0; o >>= 1) s += __shfl_xor_sync(0xffffffff, s, o);
            if (rl == 0) es_s[r] = __expf(s);
        }
    }
    __syncthreads();

    if (W_dec == nullptr) {
#pragma unroll
        for (int nf = 0; nf < 2; nf++) {
            const int cb = warp * 16 + nf * 8 + tg * 2;
            *(__half2*)&d_U[(size_t)(j0 + g) * PW + cb] =
                __floats2half2_rn(es_s[g] * (accv[nf][0] + sbav[cb]),
                                  es_s[g] * (accv[nf][1] + sbav[cb + 1]));
            *(__half2*)&d_U[(size_t)(j0 + g + 8) * PW + cb] =
                __floats2half2_rn(es_s[g + 8] * (accv[nf][2] + sbav[cb]),
                                  es_s[g + 8] * (accv[nf][3] + sbav[cb + 1]));
        }
        if (tid < 16) d_evec[j0 + tid] = es_s[tid];
    } else {
#pragma unroll
        for (int nf = 0; nf < 2; nf++) {
            const int cb = warp * 16 + nf * 8 + tg * 2;
            prod[g][cb]     = (accv[nf][0] + sbav[cb])     * swd[cb];
            prod[g][cb + 1] = (accv[nf][1] + sbav[cb + 1]) * swd[cb + 1];
            prod[g + 8][cb]     = (accv[nf][2] + sbav[cb])     * swd[cb];
            prod[g + 8][cb + 1] = (accv[nf][3] + sbav[cb + 1]) * swd[cb + 1];
        }
        __syncthreads();
        if (tid < 128) {
            const int rw = tid >> 5, rl = tid & 31;
#pragma unroll
            for (int rr = 0; rr < 4; rr++) {
                int r = rw * 4 + rr;
                float s = prod[r][rl] + prod[r][rl + 32] + prod[r][rl + 64] + prod[r][rl + 96];
#pragma unroll
                for (int o = 16; o > 0; o >>= 1) s += __shfl_xor_sync(0xffffffff, s, o);
                if (rl == 0) vdot[r] = s;
            }
        }
        __syncthreads();
        if (tid < 16) {
            d_uvec[j0 + tid] = es_s[tid] * vdot[tid];
            d_evec[j0 + tid] = es_s[tid];
        }
    }
}

// ---------------- 4. split-K fp16 GEMM: BM=128, BN=128, fused den (half2) ----------------
#define AST 136                            // 128 + 8 pad halfs
#define ABUF 4352                          // 32*136 halfs per buffer
#define SE_OFF (8 * ABUF)                  // floats after 8 half-buffers
#define GEMM_SMEM (8 * ABUF * 2 + (128 + 512) * 4)

__global__ __launch_bounds__(256, 2) void gemm_kernel()
{
    extern __shared__ __half sm[];
    float* se = (float*)(sm + SE_OFF);          // [4][32]
    float* sden = se + 128;                     // [4][128]

    const int tid = threadIdx.x;
    const int m0 = blockIdx.x * 128;
    const size_t ks = (size_t)blockIdx.y * KCHUNK;
    const int warp = tid >> 5, lane = tid & 31;
    const int wm = (warp & 3) * 32, wn = (warp >> 2) * 64;

    float acc[2][8][4];
#pragma unroll
    for (int mi = 0; mi < 2; mi++)
#pragma unroll
        for (int i = 0; i < 8; i++)
            acc[mi][i][0] = acc[mi][i][1] = acc[mi][i][2] = acc[mi][i][3] = 0.f;
    float den0 = 0.f, den1 = 0.f;

    const int r0 = tid >> 4, cc0 = (tid & 15) * 8;
    const int r1 = 16 + r0;
    const __half* Eg = d_E + ks * NN + m0;   // E[k][m]
    const __half* Ug = d_U + ks * PW;        // U[k][n]
    const float* ev = d_evec + ks;

#define ISSUE_STAGE(buf, kb)                                                      \
    do {                                                                          \
        const __half* Ea = Eg + (size_t)(kb) * NN;                                \
        const __half* Ua = Ug + (size_t)(kb) * PW;                                \
        cp16(smem_u32(&sm[(buf) * ABUF + r0 * AST + cc0]), Ea + (size_t)r0 * NN + cc0); \
        cp16(smem_u32(&sm[(buf) * ABUF + r1 * AST + cc0]), Ea + (size_t)r1 * NN + cc0); \
        cp16(smem_u32(&sm[(4 + (buf)) * ABUF + r0 * AST + cc0]), Ua + (size_t)r0 * PW + cc0); \
        cp16(smem_u32(&sm[(4 + (buf)) * ABUF + r1 * AST + cc0]), Ua + (size_t)r1 * PW + cc0); \
        if (tid >= 224) se[(buf) * 32 + tid - 224] = ev[(kb) + tid - 224];        \
        asm volatile("cp.async.commit_group;");                                   \
    } while (0)

    ISSUE_STAGE(0, 0);
    ISSUE_STAGE(1, 32);
    ISSUE_STAGE(2, 64);

    const int m2 = (tid & 63) * 2, kh = (tid >> 6) * 8;

#pragma unroll 1
    for (int it = 0; it < KITERS; it++) {
        const int buf = it & 3;
        if (it < KITERS - 2)       asm volatile("cp.async.wait_group 2;" ::: "memory");
        else if (it == KITERS - 2) asm volatile("cp.async.wait_group 1;" ::: "memory");
        else                       asm volatile("cp.async.wait_group 0;" ::: "memory");
        __syncthreads();

        if (it + 3 < KITERS) ISSUE_STAGE((it + 3) & 3, (it + 3) * 32);

#pragma unroll
        for (int k2 = 0; k2 < 8; k2++) {
            const float2 ef = __half22float2(
                *(const __half2*)&sm[buf * ABUF + (kh + k2) * AST + m2]);
            const float w = se[buf * 32 + kh + k2];
            den0 += ef.x * w;
            den1 += ef.y * w;
        }

#pragma unroll
        for (int kk = 0; kk < 2; kk++) {
            const int arow = kk * 16 + (lane & 7) + ((lane >> 4) << 3);
            const int acb = wm + ((lane >> 3) & 1) * 8;
            uint32_t a0[4], a1[4];
            ldsm_x4t(a0[0], a0[1], a0[2], a0[3],
                     smem_u32(&sm[buf * ABUF + arow * AST + acb]));
            ldsm_x4t(a1[0], a1[1], a1[2], a1[3],
                     smem_u32(&sm[buf * ABUF + arow * AST + acb + 16]));
#pragma unroll
            for (int nf = 0; nf < 4; nf++) {
                uint32_t b0, b1, b2, b3;
                ldsm_x4t(b0, b1, b2, b3,
                         smem_u32(&sm[(4 + buf) * ABUF + (kk * 16 + (lane & 15)) * AST
                                      + wn + nf * 16 + (lane >> 4) * 8]));
                float* c00 = acc[0][2 * nf];
                float* c01 = acc[0][2 * nf + 1];
                float* c10 = acc[1][2 * nf];
                float* c11 = acc[1][2 * nf + 1];
                mma_f16(c00[0], c00[1], c00[2], c00[3], a0[0], a0[1], a0[2], a0[3], b0, b1);
                mma_f16(c01[0], c01[1], c01[2], c01[3], a0[0], a0[1], a0[2], a0[3], b2, b3);
                mma_f16(c10[0], c10[1], c10[2], c10[3], a1[0], a1[1], a1[2], a1[3], b0, b1);
                mma_f16(c11[0], c11[1], c11[2], c11[3], a1[0], a1[1], a1[2], a1[3], b2, b3);
            }
        }
    }

    const int g = lane >> 2, tg = lane & 3;
    __half* P = d_part + ((size_t)blockIdx.y * NN + m0 + wm) * PW + wn;
#pragma unroll
    for (int mi = 0; mi < 2; mi++) {
#pragma unroll
        for (int fi = 0; fi < 8; fi++) {
            int col = fi * 8 + tg * 2;
            int rr0 = mi * 16 + g;
            *(__half2*)&P[(size_t)rr0 * PW + col] =
                __floats2half2_rn(acc[mi][fi][0], acc[mi][fi][1]);
            *(__half2*)&P[(size_t)(rr0 + 8) * PW + col] =
                __floats2half2_rn(acc[mi][fi][2], acc[mi][fi][3]);
        }
    }
    sden[(tid >> 6) * 128 + m2] = den0;
    sden[(tid >> 6) * 128 + m2 + 1] = den1;
    __syncthreads();
    if (tid < 128)
        d_denp[(size_t)blockIdx.y * NN + m0 + tid] =
            sden[tid] + sden[128 + tid] + sden[256 + tid] + sden[384 + tid];
#undef ISSUE_STAGE
}

// ---------------- 5. layer-3 GEMV: colsum of E weighted by u / e ----------------
#define JCH 64
#define NJC (NN / JCH)  // 64 chunks
__global__ __launch_bounds__(256) void gemv_kernel()
{
    float* gnum = d_gemv_scratch;                // [NJC][NN]
    float* gden = gnum + (size_t)NJC * NN;
    const int i0 = blockIdx.x * 1024;
    const int j0 = blockIdx.y * JCH;
    const int t = threadIdx.x;
    __shared__ float su[JCH], sev[JCH];
    if (t < JCH) { su[t] = d_uvec[j0 + t]; sev[t] = d_evec[j0 + t]; }
    __syncthreads();

    float n0 = 0.f, n1 = 0.f, n2 = 0.f, n3 = 0.f;
    float e0 = 0.f, e1 = 0.f, e2 = 0.f, e3 = 0.f;
    const __half* Eb = d_E + (size_t)j0 * NN + i0 + 2 * t;
#pragma unroll 4
    for (int j = 0; j < JCH; j++) {
        const float u = su[j], evv = sev[j];
        const __half2 a = *(const __half2*)(Eb + (size_t)j * NN);
        const __half2 b = *(const __half2*)(Eb + (size_t)j * NN + 512);
        const float2 af = __half22float2(a);
        const float2 bf = __half22float2(b);
        n0 += af.x * u;   n1 += af.y * u;
        n2 += bf.x * u;   n3 += bf.y * u;
        e0 += af.x * evv; e1 += af.y * evv;
        e2 += bf.x * evv; e3 += bf.y * evv;
    }
    const size_t base = (size_t)blockIdx.y * NN + i0 + 2 * t;
    *(float2*)&gnum[base] = make_float2(n0, n1);
    *(float2*)&gnum[base + 512] = make_float2(n2, n3);
    *(float2*)&gden[base] = make_float2(e0, e1);
    *(float2*)&gden[base + 512] = make_float2(e2, e3);
}

// ---------------- 6. finalize: out = num/den + b_dec (+mask) ----------------
__global__ __launch_bounds__(128) void finalize_kernel(
    const float* __restrict__ b_dec, const int* __restrict__ mask,
    float* __restrict__ out)
{
    const float* gnum = d_gemv_scratch;
    const float* gden = gnum + (size_t)NJC * NN;
    const int i = blockIdx.x * 128 + threadIdx.x;
    float num = 0.f, den = 0.f;
#pragma unroll 8
    for (int jc = 0; jc < NJC; jc++) {
        num += gnum[(size_t)jc * NN + i];
        den += gden[(size_t)jc * NN + i];
    }
    out[i] = (mask[i] == 0) ? __int_as_float(0xff800000)
                            : (num / den + b_dec[0]);
}

// ---------------- launch ----------------
extern "C" void kernel_launch(void* const* d_in, const int* in_sizes, int n_in,
                              void* d_out, int out_size)
{
    const float* x      = (const float*)d_in[0];
    const float* comms  = (const float*)d_in[1];
    const float* trans  = (const float*)d_in[2];
    const int*   mask   = (const int*)d_in[3];
    const float* W_enc  = (const float*)d_in[4];
    const float* b_enc  = (const float*)d_in[5];
    const float* W_ad   = (const float*)d_in[6];
    const float* b_ad   = (const float*)d_in[7];
    const float* w_att  = (const float*)d_in[8];
    // d_in[9] = b_att: cancels in row-softmax, unused
    const float* W_av   = (const float*)d_in[10];
    const float* b_av   = (const float*)d_in[11];
    const float* W_dec  = (const float*)d_in[12];
    const float* b_dec  = (const float*)d_in[13];
    float* out = (float*)d_out;

    cudaFuncSetAttribute(gemm_kernel, cudaFuncAttributeMaxDynamicSharedMemorySize,
                         GEMM_SMEM);

    encode_kernel<<<NN / 16, 128>>>(x, comms, W_enc, b_enc);
    buildE_kernel<<<(NN * (size_t)NN) / (256 * 8), 256>>>(trans);

    for (int k = 0; k < 3; k++) {
        computeU_kernel<<<NN / 16, 256>>>(W_ad + (size_t)k * DQ * DQ,
                                          b_ad + (size_t)k * DQ,
                                          w_att + (size_t)k * 2 * DQ,   // wa = first half
                                          W_av + (size_t)k * DQ * DQ,
                                          b_av + (size_t)k * DQ,
                                          k > 0,
                                          (k == 2) ? W_dec : nullptr);
        if (k < 2)
            gemm_kernel<<<dim3(NN / 128, SPLITK), 256, GEMM_SMEM>>>();
    }
    gemv_kernel<<<dim3(4, NJC), 256>>>();
    finalize_kernel<<<NN / 128, 128>>>(b_dec, mask, out);
}